// round 2
// baseline (speedup 1.0000x reference)
#include <cuda_runtime.h>
#include <cuda_bf16.h>
#include <cstdint>

// PDF sampler: per ray, ND=64 weights -> padded normalized CDF (65 entries),
// invert at NS=32 deterministic u's, merge with original 64 offsets -> 96 sorted.
//
// Layout: one warp per ray. 8 warps (256 threads) per block.

#define ND 64
#define NS 32
#define NOUT 96
#define EPS 1e-5f
#define WARPS_PER_BLOCK 8

__global__ __launch_bounds__(WARPS_PER_BLOCK * 32)
void pdf_sampler_kernel(const float* __restrict__ weights,
                        const float* __restrict__ s_offsets,
                        float* __restrict__ out,
                        int num_rays) {
    __shared__ float s_cdf[WARPS_PER_BLOCK][ND + 1];   // 65
    __shared__ float s_off[WARPS_PER_BLOCK][ND];
    __shared__ float s_new[WARPS_PER_BLOCK][NS];
    __shared__ float s_out[WARPS_PER_BLOCK][NOUT];

    const int warp = threadIdx.x >> 5;
    const int lane = threadIdx.x & 31;
    const int ray  = blockIdx.x * WARPS_PER_BLOCK + warp;
    if (ray >= num_rays) return;

    // ---- coalesced loads: 64 floats per ray as 32 float2 ----
    const float2 wv = reinterpret_cast<const float2*>(weights   + (size_t)ray * ND)[lane];
    const float2 ov = reinterpret_cast<const float2*>(s_offsets + (size_t)ray * ND)[lane];

    s_off[warp][2 * lane]     = ov.x;
    s_off[warp][2 * lane + 1] = ov.y;

    // ---- inclusive warp scan over pair sums -> cumsum of 64 weights ----
    float pair = wv.x + wv.y;
    float scan = pair;
    #pragma unroll
    for (int d = 1; d < 32; d <<= 1) {
        float n = __shfl_up_sync(0xffffffffu, scan, d);
        if (lane >= d) scan += n;
    }
    // scan = sum(w[0 .. 2*lane+1]) inclusive
    const float total = __shfl_sync(0xffffffffu, scan, 31);
    const float pad   = fmaxf(EPS - total, 0.0f);       // relu(EPS - sum)
    const float inv   = 1.0f / (total + pad);           // cdf normalization
    const float pad64 = pad * (1.0f / (float)ND);

    // padded cumsum: cum'_k = cum_k + (k+1)*pad/64 ; cdf[k+1] = cum'_k * inv
    const float cum_even = scan - wv.y;                 // sum(w[0..2*lane])
    s_cdf[warp][2 * lane + 1] = (cum_even + (float)(2 * lane + 1) * pad64) * inv;
    s_cdf[warp][2 * lane + 2] = (scan     + (float)(2 * lane + 2) * pad64) * inv;
    if (lane == 0) s_cdf[warp][0] = 0.0f;
    __syncwarp();

    // ---- invert CDF at u = (lane + 0.5)/32, searchsorted side='right' ----
    const float u = ((float)lane + 0.5f) * (1.0f / (float)NS);
    const float* cdf = s_cdf[warp];
    // upper_bound over 65 entries: first idx with cdf[idx] > u. range 65 -> 7 iters.
    int lo = 0, hi = ND + 1;
    #pragma unroll
    for (int it = 0; it < 7; ++it) {
        if (lo < hi) {
            int mid = (lo + hi) >> 1;
            if (cdf[mid] <= u) lo = mid + 1; else hi = mid;
        }
    }
    const int idx = lo;                                  // in [1, 64]
    const int il  = min(max(idx - 1, 0), ND - 1);
    const int ir  = min(idx, ND - 1);

    const float cl = cdf[il];
    const float cr = cdf[ir];
    const float ol = s_off[warp][il];
    const float orr = s_off[warp][ir];

    const float num = u - cl;
    const float den = cr - cl;
    // replicate nan_to_num((u-cl)/(cr-cl)) then clip [0,1]:
    //   den!=0 -> finite quotient, clamp; den==0 -> 0/0=nan->0, +x/0=inf->1, -x/0=-inf->0
    float t;
    if (den != 0.0f) t = num / den;
    else             t = (num > 0.0f) ? 1.0f : 0.0f;
    t = fminf(fmaxf(t, 0.0f), 1.0f);

    const float sn = fmaf(t, orr - ol, ol);
    s_new[warp][lane] = sn;
    __syncwarp();

    // ---- merge two sorted lists via merge-path ranking ----
    // a = s_new (32), b = s_off (64)
    // pos(a[i]) = i + |{ b <= a[i] }|   (non-strict upper bound in b)
    // pos(b[j]) = j + |{ a <  b[j] }|   (strict lower bound in a)  -> bijection on [0,96)
    {
        // rank of this lane's s_new element among s_off: range 64 -> 7 iters
        const float* boff = s_off[warp];
        int l = 0, h = ND;
        #pragma unroll
        for (int it = 0; it < 7; ++it) {
            if (l < h) {
                int mid = (l + h) >> 1;
                if (boff[mid] <= sn) l = mid + 1; else h = mid;
            }
        }
        s_out[warp][lane + l] = sn;
    }
    {
        const float* anew = s_new[warp];
        // element 2*lane (value ov.x): range 32 -> 6 iters
        int l = 0, h = NS;
        #pragma unroll
        for (int it = 0; it < 6; ++it) {
            if (l < h) {
                int mid = (l + h) >> 1;
                if (anew[mid] < ov.x) l = mid + 1; else h = mid;
            }
        }
        s_out[warp][2 * lane + l] = ov.x;
        // element 2*lane+1 (value ov.y): range 32 -> 6 iters
        l = 0; h = NS;
        #pragma unroll
        for (int it = 0; it < 6; ++it) {
            if (l < h) {
                int mid = (l + h) >> 1;
                if (anew[mid] < ov.y) l = mid + 1; else h = mid;
            }
        }
        s_out[warp][2 * lane + 1 + l] = ov.y;
    }
    __syncwarp();

    // ---- coalesced output: 96 floats = 3 x 128B aligned stores ----
    float* o = out + (size_t)ray * NOUT;
    o[lane]      = s_out[warp][lane];
    o[lane + 32] = s_out[warp][lane + 32];
    o[lane + 64] = s_out[warp][lane + 64];
}

extern "C" void kernel_launch(void* const* d_in, const int* in_sizes, int n_in,
                              void* d_out, int out_size) {
    const float* weights   = (const float*)d_in[0];
    const float* s_offsets = (const float*)d_in[1];
    float* out = (float*)d_out;

    const int num_rays = in_sizes[0] / ND;
    const int blocks = (num_rays + WARPS_PER_BLOCK - 1) / WARPS_PER_BLOCK;
    pdf_sampler_kernel<<<blocks, WARPS_PER_BLOCK * 32>>>(weights, s_offsets, out, num_rays);
}

// round 3
// speedup vs baseline: 1.1357x; 1.1357x over previous
#include <cuda_runtime.h>
#include <cuda_bf16.h>
#include <cstdint>

// PDF sampler, warp-per-ray, analytic ranks against the fixed u-grid.
// u_j = (2j+1)/64 exactly representable; all searches replaced by O(1)
// counts + a 32-write scatter per warp.

#define ND 64
#define NS 32
#define NOUT 96
#define EPS 1e-5f
#define WPB 8

static __device__ __forceinline__ int count_u_below(float c) {
    // exact #{ j in [0,32) : (2j+1)/64 < c }
    int n = (int)fmaf(32.0f, c, 0.5f);      // candidate (±1 of truth)
    n = min(max(n, 0), 32);
    while (n > 0 && (float)(2 * n - 1) * 0.015625f >= c) --n;   // exact cmp
    while (n < 32 && (float)(2 * n + 1) * 0.015625f < c) ++n;   // exact cmp
    return n;
}

__global__ __launch_bounds__(WPB * 32)
void pdf_sampler_kernel(const float* __restrict__ weights,
                        const float* __restrict__ s_offsets,
                        float* __restrict__ out,
                        int num_rays) {
    __shared__ float s_cdf[WPB][ND + 1];
    __shared__ float s_off[WPB][ND];
    __shared__ float s_new[WPB][NS];
    __shared__ int   s_idx[WPB][NS];

    const int warp = threadIdx.x >> 5;
    const int lane = threadIdx.x & 31;
    const int ray  = blockIdx.x * WPB + warp;
    if (ray >= num_rays) return;   // whole-warp uniform (1 ray per warp)

    const float2 wv = reinterpret_cast<const float2*>(weights   + (size_t)ray * ND)[lane];
    const float2 ov = reinterpret_cast<const float2*>(s_offsets + (size_t)ray * ND)[lane];
    reinterpret_cast<float2*>(s_off[warp])[lane] = ov;

    // ---- inclusive warp scan over pair sums ----
    float scan = wv.x + wv.y;
    #pragma unroll
    for (int d = 1; d < 32; d <<= 1) {
        float v = __shfl_up_sync(0xffffffffu, scan, d);
        if (lane >= d) scan += v;
    }
    const float total = __shfl_sync(0xffffffffu, scan, 31);
    const float pad   = fmaxf(EPS - total, 0.0f);
    const float inv   = 1.0f / (total + pad);
    const float pad64 = pad * (1.0f / 64.0f);

    const float cum_even = scan - wv.y;
    const float c1 = (cum_even + (float)(2 * lane + 1) * pad64) * inv;  // cdf[2l+1]
    const float c2 = (scan     + (float)(2 * lane + 2) * pad64) * inv;  // cdf[2l+2]
    s_cdf[warp][2 * lane + 1] = c1;
    s_cdf[warp][2 * lane + 2] = c2;
    if (lane == 0) s_cdf[warp][0] = 0.0f;

    // ---- analytic counts n_k = #{u < cdf[k]} ----
    int n1 = count_u_below(c1);              // raw n_{2l+1}
    int n2 = count_u_below(c2);              // raw n_{2l+2}

    // enforce monotone n via warp max-scan (guards ulp-level scan inversions)
    int P = max(n1, n2);
    #pragma unroll
    for (int d = 1; d < 32; d <<= 1) {
        int v = __shfl_up_sync(0xffffffffu, P, d);
        if (lane >= d) P = max(P, v);
    }
    int Pprev = __shfl_up_sync(0xffffffffu, P, 1);
    if (lane == 0) Pprev = 0;
    n1 = max(n1, Pprev);     // final N_{2l+1}
    n2 = P;                  // final N_{2l+2} = max(Pprev, n1, n2)
    int n3 = __shfl_down_sync(0xffffffffu, n1, 1);  // N_{2l+3}
    if (lane == 31) n3 = 32;
    const int n_even = Pprev;                        // N_{2l}

    // ---- scatter bin indices: u_i in [N_k, N_{k+1}) -> idx = k+1 ----
    for (int i = n1; i < n2; ++i) s_idx[warp][i] = 2 * lane + 2;
    for (int i = n2; i < n3; ++i) s_idx[warp][i] = 2 * lane + 3;
    if (lane == 0) for (int i = 0; i < n1; ++i) s_idx[warp][i] = 1;
    __syncwarp();

    // ---- invert + interpolate (lane handles u_lane) ----
    const float u  = (float)(2 * lane + 1) * 0.015625f;
    const int idx  = s_idx[warp][lane];              // in [1, 64]
    const int il   = min(idx - 1, ND - 1);
    const int ir   = min(idx, ND - 1);

    const float cl  = s_cdf[warp][il];
    const float cr  = s_cdf[warp][ir];
    const float ol  = s_off[warp][il];
    const float orr = s_off[warp][ir];

    const float den = cr - cl;
    float t = (den != 0.0f) ? (u - cl) / den : ((u > cl) ? 1.0f : 0.0f);
    t = fminf(fmaxf(t, 0.0f), 1.0f);
    const float sn = fmaf(t, orr - ol, ol);          // sn in [off[il], off[ir]]
    s_new[warp][lane] = sn;

    // ---- exact rank of sn among offsets (non-strict): starts valid at idx ----
    int r = idx;
    while (r < ND && s_off[warp][r] <= sn) ++r;      // ~0 iterations typical
    __syncwarp();

    // flag: sn hit off[idx] exactly (breaks the analytic b-rank) — rare
    const unsigned bal = __ballot_sync(0xffffffffu, r != idx);

    float* o = out + (size_t)ray * NOUT;
    o[lane + r] = sn;                                // pos_a = i + rank_a

    int rbx, rby;
    if (bal == 0u) {
        rbx = n_even;   // rank_b(off[2l])   = N_{2l}
        rby = n1;       // rank_b(off[2l+1]) = N_{2l+1}
    } else {
        // honest strict lower bound in s_new (sorted by construction)
        const float* a = s_new[warp];
        int l = 0, h = NS;
        #pragma unroll
        for (int it = 0; it < 6; ++it) {
            if (l < h) { int mid = (l + h) >> 1; if (a[mid] < ov.x) l = mid + 1; else h = mid; }
        }
        rbx = l;
        l = 0; h = NS;
        #pragma unroll
        for (int it = 0; it < 6; ++it) {
            if (l < h) { int mid = (l + h) >> 1; if (a[mid] < ov.y) l = mid + 1; else h = mid; }
        }
        rby = l;
    }
    o[2 * lane + rbx]     = ov.x;                    // pos_b = j + rank_b
    o[2 * lane + 1 + rby] = ov.y;
}

extern "C" void kernel_launch(void* const* d_in, const int* in_sizes, int n_in,
                              void* d_out, int out_size) {
    const float* weights   = (const float*)d_in[0];
    const float* s_offsets = (const float*)d_in[1];
    float* out = (float*)d_out;

    const int num_rays = in_sizes[0] / ND;
    const int blocks = (num_rays + WPB - 1) / WPB;
    pdf_sampler_kernel<<<blocks, WPB * 32>>>(weights, s_offsets, out, num_rays);
}

// round 4
// speedup vs baseline: 1.1926x; 1.0501x over previous
#include <cuda_runtime.h>
#include <cuda_bf16.h>
#include <cstdint>

// PDF sampler, warp-per-ray. Analytic ranks vs the fixed u-grid u_j=(2j+1)/64,
// smem-staged merge, float4-coalesced output.

#define ND 64
#define NS 32
#define NOUT 96
#define EPS 1e-5f
#define WPB 8

static __device__ __forceinline__ int count_u_below(float c) {
    // exact #{ j in [0,32) : (2j+1)/64 < c }.
    // x = 32*c is exact (pow2 scale); x+0.5 exactly representable here, so
    // trunc(x+0.5) is >= truth and <= truth+1 (over only at exact half-integers).
    int n = (int)fmaf(32.0f, c, 0.5f);
    n = min(max(n, 0), 32);
    if (n > 0 && (float)(2 * n - 1) * 0.015625f >= c) --n;  // exact cmp
    return n;
}

__global__ __launch_bounds__(WPB * 32)
void pdf_sampler_kernel(const float* __restrict__ weights,
                        const float* __restrict__ s_offsets,
                        float* __restrict__ out,
                        int num_rays) {
    __shared__ float s_cdf[WPB][ND + 1];
    __shared__ float s_off[WPB][ND];
    __shared__ float s_new[WPB][NS];
    __shared__ int   s_idx[WPB][NS];
    __shared__ __align__(16) float s_out[WPB][NOUT];

    const int warp = threadIdx.x >> 5;
    const int lane = threadIdx.x & 31;
    const int ray  = blockIdx.x * WPB + warp;
    if (ray >= num_rays) return;   // warp-uniform

    const float2 wv = reinterpret_cast<const float2*>(weights   + (size_t)ray * ND)[lane];
    const float2 ov = reinterpret_cast<const float2*>(s_offsets + (size_t)ray * ND)[lane];
    reinterpret_cast<float2*>(s_off[warp])[lane] = ov;

    // ---- inclusive warp scan over pair sums ----
    float scan = wv.x + wv.y;
    #pragma unroll
    for (int d = 1; d < 32; d <<= 1) {
        float v = __shfl_up_sync(0xffffffffu, scan, d);
        if (lane >= d) scan += v;
    }
    const float total = __shfl_sync(0xffffffffu, scan, 31);
    const float pad   = fmaxf(EPS - total, 0.0f);
    const float inv   = 1.0f / (total + pad);
    const float pad64 = pad * (1.0f / 64.0f);

    const float cum_even = scan - wv.y;
    const float c1 = (cum_even + (float)(2 * lane + 1) * pad64) * inv;  // cdf[2l+1]
    const float c2 = (scan     + (float)(2 * lane + 2) * pad64) * inv;  // cdf[2l+2]
    s_cdf[warp][2 * lane + 1] = c1;
    s_cdf[warp][2 * lane + 2] = c2;
    if (lane == 0) s_cdf[warp][0] = 0.0f;

    // ---- analytic counts n_k = #{u < cdf[k]} ----
    int n1 = count_u_below(c1);
    int n2 = count_u_below(c2);

    // enforce monotone N via warp max-scan (guards ulp-level scan inversions)
    int P = max(n1, n2);
    #pragma unroll
    for (int d = 1; d < 32; d <<= 1) {
        int v = __shfl_up_sync(0xffffffffu, P, d);
        if (lane >= d) P = max(P, v);
    }
    int Pprev = __shfl_up_sync(0xffffffffu, P, 1);
    if (lane == 0) Pprev = 0;
    n1 = max(n1, Pprev);     // N_{2l+1}
    n2 = P;                  // N_{2l+2}
    int n3 = __shfl_down_sync(0xffffffffu, n1, 1);  // N_{2l+3}
    if (lane == 31) n3 = 32;
    const int n_even = Pprev;                        // N_{2l}

    // ---- scatter bin indices: u_i in [N_k, N_{k+1}) -> idx = k+1 ----
    for (int i = n1; i < n2; ++i) s_idx[warp][i] = 2 * lane + 2;
    for (int i = n2; i < n3; ++i) s_idx[warp][i] = 2 * lane + 3;
    if (lane == 0) for (int i = 0; i < n1; ++i) s_idx[warp][i] = 1;
    __syncwarp();

    // ---- invert + interpolate (lane handles u_lane) ----
    const float u  = (float)(2 * lane + 1) * 0.015625f;
    const int idx  = s_idx[warp][lane];              // in [1, 64]
    const int il   = idx - 1;                        // <= 63
    const int ir   = min(idx, ND - 1);

    const float cl  = s_cdf[warp][il];
    const float cr  = s_cdf[warp][ir];
    const float ol  = s_off[warp][il];
    const float orr = s_off[warp][ir];

    const float den = cr - cl;
    float t = (den != 0.0f) ? (u - cl) / den : ((u > cl) ? 1.0f : 0.0f);
    t = fminf(fmaxf(t, 0.0f), 1.0f);
    const float sn = fmaf(t, orr - ol, ol);          // sn in [off[il], off[ir]]
    s_new[warp][lane] = sn;

    // exact non-strict rank of sn among offsets; valid start at idx
    int r = idx;
    while (r < ND && s_off[warp][r] <= sn) ++r;      // ~0 iterations typical
    __syncwarp();

    // analytic b-rank valid unless some sn hit an offset exactly (rare)
    const unsigned bal = __ballot_sync(0xffffffffu, r != idx);

    int rbx, rby;
    if (bal == 0u) {
        rbx = n_even;   // rank_b(off[2l])   = N_{2l}
        rby = n1;       // rank_b(off[2l+1]) = N_{2l+1}
    } else {
        const float* a = s_new[warp];
        int l = 0, h = NS;
        #pragma unroll
        for (int it = 0; it < 6; ++it) {
            if (l < h) { int mid = (l + h) >> 1; if (a[mid] < ov.x) l = mid + 1; else h = mid; }
        }
        rbx = l;
        l = 0; h = NS;
        #pragma unroll
        for (int it = 0; it < 6; ++it) {
            if (l < h) { int mid = (l + h) >> 1; if (a[mid] < ov.y) l = mid + 1; else h = mid; }
        }
        rby = l;
    }

    // ---- merge scatter into shared (cheap), then coalesced float4 stores ----
    s_out[warp][lane + r]           = sn;    // pos_a = i + rank_a
    s_out[warp][2 * lane + rbx]     = ov.x;  // pos_b = j + rank_b
    s_out[warp][2 * lane + 1 + rby] = ov.y;
    __syncwarp();

    if (lane < 24) {
        float4 v = reinterpret_cast<const float4*>(s_out[warp])[lane];
        reinterpret_cast<float4*>(out + (size_t)ray * NOUT)[lane] = v;
    }
}

extern "C" void kernel_launch(void* const* d_in, const int* in_sizes, int n_in,
                              void* d_out, int out_size) {
    const float* weights   = (const float*)d_in[0];
    const float* s_offsets = (const float*)d_in[1];
    float* out = (float*)d_out;

    const int num_rays = in_sizes[0] / ND;
    const int blocks = (num_rays + WPB - 1) / WPB;
    pdf_sampler_kernel<<<blocks, WPB * 32>>>(weights, s_offsets, out, num_rays);
}

// round 5
// speedup vs baseline: 1.2379x; 1.0380x over previous
#include <cuda_runtime.h>
#include <cuda_bf16.h>
#include <cstdint>

// PDF sampler, warp-per-ray. Analytic ranks vs the fixed u-grid u_j=(2j+1)/64,
// fused (cdf,off) float2 table, fast division, smem-staged merge, float4 output.

#define ND 64
#define NS 32
#define NOUT 96
#define EPS 1e-5f
#define WPB 8

static __device__ __forceinline__ int count_u_below(float c) {
    // exact #{ j in [0,32) : (2j+1)/64 < c }.
    int n = (int)fmaf(32.0f, c, 0.5f);      // >= truth, <= truth+1
    n = min(max(n, 0), 32);
    if (n > 0 && (float)(2 * n - 1) * 0.015625f >= c) --n;  // exact cmp
    return n;
}

__global__ __launch_bounds__(WPB * 32)
void pdf_sampler_kernel(const float* __restrict__ weights,
                        const float* __restrict__ s_offsets,
                        float* __restrict__ out,
                        int num_rays) {
    __shared__ __align__(16) float2 s_co[WPB][ND];   // (cdf[k], off[k]), k<64
    __shared__ float s_new[WPB][NS];
    __shared__ int   s_idx[WPB][NS];
    __shared__ __align__(16) float s_out[WPB][NOUT];

    const int warp = threadIdx.x >> 5;
    const int lane = threadIdx.x & 31;
    const int ray  = blockIdx.x * WPB + warp;
    if (ray >= num_rays) return;   // warp-uniform

    const float2 wv = reinterpret_cast<const float2*>(weights   + (size_t)ray * ND)[lane];
    const float2 ov = reinterpret_cast<const float2*>(s_offsets + (size_t)ray * ND)[lane];

    // ---- inclusive warp scan over pair sums ----
    float scan = wv.x + wv.y;
    #pragma unroll
    for (int d = 1; d < 32; d <<= 1) {
        float v = __shfl_up_sync(0xffffffffu, scan, d);
        if (lane >= d) scan += v;
    }
    const float total = __shfl_sync(0xffffffffu, scan, 31);
    const float pad   = fmaxf(EPS - total, 0.0f);
    const float inv   = __fdividef(1.0f, total + pad);
    const float pad64 = pad * (1.0f / 64.0f);

    const float cum_even = scan - wv.y;
    const float c1 = (cum_even + (float)(2 * lane + 1) * pad64) * inv;  // cdf[2l+1]
    const float c2 = (scan     + (float)(2 * lane + 2) * pad64) * inv;  // cdf[2l+2]

    // fused table: s_co[k] = (cdf[k], off[k]).
    // cdf[2l] comes from lane l-1's c2 (cdf[0] = 0).
    float c2p = __shfl_up_sync(0xffffffffu, c2, 1);
    if (lane == 0) c2p = 0.0f;
    s_co[warp][2 * lane]     = make_float2(c2p, ov.x);
    s_co[warp][2 * lane + 1] = make_float2(c1,  ov.y);

    // ---- analytic counts n_k = #{u < cdf[k]} ----
    int n1 = count_u_below(c1);
    int n2 = count_u_below(c2);

    // enforce monotone N via warp max-scan (guards ulp-level scan inversions)
    int P = max(n1, n2);
    #pragma unroll
    for (int d = 1; d < 32; d <<= 1) {
        int v = __shfl_up_sync(0xffffffffu, P, d);
        if (lane >= d) P = max(P, v);
    }
    int Pprev = __shfl_up_sync(0xffffffffu, P, 1);
    if (lane == 0) Pprev = 0;
    n1 = max(n1, Pprev);     // N_{2l+1}
    n2 = P;                  // N_{2l+2}
    int n3 = __shfl_down_sync(0xffffffffu, n1, 1);  // N_{2l+3}
    if (lane == 31) n3 = 32;
    const int n_even = Pprev;                        // N_{2l}

    // ---- scatter bin indices: u_i in [N_k, N_{k+1}) -> idx = k+1 ----
    int* sidx = s_idx[warp];
    for (int i = n1; i < n2; ++i) sidx[i] = 2 * lane + 2;
    for (int i = n2; i < n3; ++i) sidx[i] = 2 * lane + 3;
    if (lane == 0) for (int i = 0; i < n1; ++i) sidx[i] = 1;
    __syncwarp();

    // ---- invert + interpolate (lane handles u_lane) ----
    const float u  = (float)(2 * lane + 1) * 0.015625f;
    const int idx  = sidx[lane];                     // in [1, 64]
    const int il   = idx - 1;                        // <= 63
    const int ir   = min(idx, ND - 1);

    const float2 L = s_co[warp][il];                 // (cl, ol)
    const float2 R = s_co[warp][ir];                 // (cr, or)

    const float num = u - L.x;
    const float den = R.x - L.x;
    float t = (den != 0.0f) ? __fdividef(num, den) : ((num > 0.0f) ? 1.0f : 0.0f);
    t = fminf(fmaxf(t, 0.0f), 1.0f);                 // also squashes 0*inf NaN -> 0
    const float sn = fmaf(t, R.y - L.y, L.y);        // sn in [off[il], off[ir]]
    s_new[warp][lane] = sn;

    // exact non-strict rank of sn among offsets; valid start at idx
    int r = idx;
    while (r < ND && s_co[warp][r].y <= sn) ++r;     // ~0 iterations typical
    __syncwarp();

    // analytic b-rank valid unless some sn hit an offset exactly (rare)
    const unsigned bal = __ballot_sync(0xffffffffu, r != idx);

    int rbx, rby;
    if (bal == 0u) {
        rbx = n_even;   // rank_b(off[2l])   = N_{2l}
        rby = n1;       // rank_b(off[2l+1]) = N_{2l+1}
    } else {
        const float* a = s_new[warp];
        int l = 0, h = NS;
        #pragma unroll
        for (int it = 0; it < 6; ++it) {
            if (l < h) { int mid = (l + h) >> 1; if (a[mid] < ov.x) l = mid + 1; else h = mid; }
        }
        rbx = l;
        l = 0; h = NS;
        #pragma unroll
        for (int it = 0; it < 6; ++it) {
            if (l < h) { int mid = (l + h) >> 1; if (a[mid] < ov.y) l = mid + 1; else h = mid; }
        }
        rby = l;
    }

    // ---- merge scatter into shared, then coalesced float4 stores ----
    s_out[warp][lane + r]           = sn;    // pos_a = i + rank_a
    s_out[warp][2 * lane + rbx]     = ov.x;  // pos_b = j + rank_b
    s_out[warp][2 * lane + 1 + rby] = ov.y;
    __syncwarp();

    if (lane < 24) {
        float4 v = reinterpret_cast<const float4*>(s_out[warp])[lane];
        reinterpret_cast<float4*>(out + (size_t)ray * NOUT)[lane] = v;
    }
}

extern "C" void kernel_launch(void* const* d_in, const int* in_sizes, int n_in,
                              void* d_out, int out_size) {
    const float* weights   = (const float*)d_in[0];
    const float* s_offsets = (const float*)d_in[1];
    float* out = (float*)d_out;

    const int num_rays = in_sizes[0] / ND;
    const int blocks = (num_rays + WPB - 1) / WPB;
    pdf_sampler_kernel<<<blocks, WPB * 32>>>(weights, s_offsets, out, num_rays);
}

// round 6
// speedup vs baseline: 1.4385x; 1.1620x over previous
#include <cuda_runtime.h>
#include <cuda_bf16.h>
#include <cstdint>

// PDF sampler, warp-per-ray. Analytic ranks vs fixed u-grid u_j=(2j+1)/64.
// Ballot-guarded monotone fast path (no max-scan), fused (cdf,off) table,
// smem-staged merge, float4-coalesced output.

#define ND 64
#define NS 32
#define NOUT 96
#define EPS 1e-5f
#define WPB 8

static __device__ __forceinline__ int count_u_below(float c) {
    // exact #{ j in [0,32) : (2j+1)/64 < c }
    int n = (int)fmaf(32.0f, c, 0.5f);      // >= truth, <= truth+1
    n = min(max(n, 0), 32);
    if (n > 0 && (float)(2 * n - 1) * 0.015625f >= c) --n;  // exact cmp
    return n;
}

__global__ __launch_bounds__(WPB * 32)
void pdf_sampler_kernel(const float* __restrict__ weights,
                        const float* __restrict__ s_offsets,
                        float* __restrict__ out,
                        int num_rays) {
    __shared__ __align__(16) float2 s_co[WPB][ND];   // (cdf[k], off[k]), k<64
    __shared__ float s_new[WPB][NS];                 // fallback only
    __shared__ int   s_idx[WPB][NS];
    __shared__ __align__(16) float s_out[WPB][NOUT];

    const int warp = threadIdx.x >> 5;
    const int lane = threadIdx.x & 31;
    const int ray  = blockIdx.x * WPB + warp;
    if (ray >= num_rays) return;   // warp-uniform

    const float2 wv = reinterpret_cast<const float2*>(weights   + (size_t)ray * ND)[lane];
    const float2 ov = reinterpret_cast<const float2*>(s_offsets + (size_t)ray * ND)[lane];

    // ---- inclusive warp scan over pair sums ----
    float scan = wv.x + wv.y;
    #pragma unroll
    for (int d = 1; d < 32; d <<= 1) {
        float v = __shfl_up_sync(0xffffffffu, scan, d);
        if (lane >= d) scan += v;
    }
    const float total = __shfl_sync(0xffffffffu, scan, 31);
    const float pad   = fmaxf(EPS - total, 0.0f);
    const float inv   = __fdividef(1.0f, total + pad);
    const float pad64 = pad * (1.0f / 64.0f);

    const float cum_even = scan - wv.y;
    const float c1 = (cum_even + (float)(2 * lane + 1) * pad64) * inv;  // cdf[2l+1]
    const float c2 = (scan     + (float)(2 * lane + 2) * pad64) * inv;  // cdf[2l+2]

    // fused table: s_co[k] = (cdf[k], off[k]); cdf[2l] from lane l-1's c2.
    float c2p = __shfl_up_sync(0xffffffffu, c2, 1);
    if (lane == 0) c2p = 0.0f;
    s_co[warp][2 * lane]     = make_float2(c2p, ov.x);
    s_co[warp][2 * lane + 1] = make_float2(c1,  ov.y);

    // ---- analytic counts N_k = #{u < cdf[k]} ----
    int n1 = count_u_below(c1);              // N_{2l+1}
    int n2 = count_u_below(c2);              // N_{2l+2}
    n2 = max(n1, n2);                        // in-lane monotone (free)
    if (lane == 31) n2 = 32;                 // cdf[64]=1: exact by definition

    int ne = __shfl_up_sync(0xffffffffu, n2, 1);   // N_{2l}
    if (lane == 0) ne = 0;

    // cross-lane monotone? (ulp-level scan inversion guard; ~never fires)
    if (__ballot_sync(0xffffffffu, n1 < ne)) {
        int P = n2;
        #pragma unroll
        for (int d = 1; d < 32; d <<= 1) {
            int v = __shfl_up_sync(0xffffffffu, P, d);
            if (lane >= d) P = max(P, v);
        }
        ne = __shfl_up_sync(0xffffffffu, P, 1);
        if (lane == 0) ne = 0;
        n1 = max(n1, ne);
        n2 = P;
    }

    // ---- scatter bin indices: consecutive disjoint ranges cover [0,32) ----
    int* sidx = s_idx[warp];
    for (int i = ne; i < n1; ++i) sidx[i] = 2 * lane + 1;
    for (int i = n1; i < n2; ++i) sidx[i] = 2 * lane + 2;
    __syncwarp();

    // ---- invert + interpolate (lane handles u_lane) ----
    const float u  = (float)(2 * lane + 1) * 0.015625f;
    const int idx  = sidx[lane];                     // in [1, 64]
    const int il   = idx - 1;                        // <= 63
    const int ir   = min(idx, ND - 1);

    const float2 L = s_co[warp][il];                 // (cl, ol)
    const float2 R = s_co[warp][ir];                 // (cr, or)

    const float num = u - L.x;
    const float den = R.x - L.x;
    float t = (den != 0.0f) ? __fdividef(num, den) : ((num > 0.0f) ? 1.0f : 0.0f);
    t = fminf(fmaxf(t, 0.0f), 1.0f);                 // squashes 0*inf NaN -> 0
    const float sn = fmaf(t, R.y - L.y, L.y);        // sn in [off[il], off[ir]]

    // exact non-strict rank of sn among offsets; valid start at idx
    int r = idx;
    while (r < ND && s_co[warp][r].y <= sn) ++r;     // ~0 iterations typical

    // analytic b-rank valid unless some sn hit an offset exactly (rare)
    int rbx = ne, rby = n1;
    if (__ballot_sync(0xffffffffu, r != idx)) {
        s_new[warp][lane] = sn;
        __syncwarp();
        const float* a = s_new[warp];
        int l = 0, h = NS;
        #pragma unroll
        for (int it = 0; it < 6; ++it) {
            if (l < h) { int mid = (l + h) >> 1; if (a[mid] < ov.x) l = mid + 1; else h = mid; }
        }
        rbx = l;
        l = 0; h = NS;
        #pragma unroll
        for (int it = 0; it < 6; ++it) {
            if (l < h) { int mid = (l + h) >> 1; if (a[mid] < ov.y) l = mid + 1; else h = mid; }
        }
        rby = l;
    }

    // ---- merge scatter into shared, then coalesced float4 stores ----
    s_out[warp][lane + r]           = sn;    // pos_a = i + rank_a
    s_out[warp][2 * lane + rbx]     = ov.x;  // pos_b = j + rank_b
    s_out[warp][2 * lane + 1 + rby] = ov.y;
    __syncwarp();

    if (lane < 24) {
        float4 v = reinterpret_cast<const float4*>(s_out[warp])[lane];
        reinterpret_cast<float4*>(out + (size_t)ray * NOUT)[lane] = v;
    }
}

extern "C" void kernel_launch(void* const* d_in, const int* in_sizes, int n_in,
                              void* d_out, int out_size) {
    const float* weights   = (const float*)d_in[0];
    const float* s_offsets = (const float*)d_in[1];
    float* out = (float*)d_out;

    const int num_rays = in_sizes[0] / ND;
    const int blocks = (num_rays + WPB - 1) / WPB;
    pdf_sampler_kernel<<<blocks, WPB * 32>>>(weights, s_offsets, out, num_rays);
}

// round 7
// speedup vs baseline: 1.6497x; 1.1468x over previous
#include <cuda_runtime.h>
#include <cuda_bf16.h>
#include <cstdint>

// PDF sampler: 2 rays per warp (16 lanes/ray, 4 elems/lane).
// Analytic ranks vs fixed u-grid u_j=(2j+1)/64, segmented width-16 scans,
// fused (cdf,off) table, smem-staged merge, dense float4 output.

#define ND 64
#define NS 32
#define NOUT 96
#define EPS 1e-5f
#define WPB 8
#define FULL 0xffffffffu

static __device__ __forceinline__ int count_u_below(float c) {
    // exact #{ j in [0,32) : (2j+1)/64 < c }
    int n = (int)fmaf(32.0f, c, 0.5f);      // >= truth, <= truth+1
    n = min(max(n, 0), 32);
    if (n > 0 && (float)(2 * n - 1) * 0.015625f >= c) --n;  // exact cmp
    return n;
}

__global__ __launch_bounds__(WPB * 32)
void pdf_sampler_kernel(const float* __restrict__ weights,
                        const float* __restrict__ s_offsets,
                        float* __restrict__ out,
                        int num_rays) {
    __shared__ __align__(16) float2 s_co[WPB][2][ND];   // (cdf[k], off[k])
    __shared__ __align__(16) float  s_new[WPB][2][NS];  // fallback only
    __shared__ __align__(16) int    s_idx[WPB][2][NS];
    __shared__ __align__(16) float  s_out[WPB][2 * NOUT];

    const int warp = threadIdx.x >> 5;
    const int lane = threadIdx.x & 31;
    const int half = lane >> 4;          // which ray within the warp
    const int hl   = lane & 15;          // lane within 16-lane segment

    const int ray_base = (blockIdx.x * WPB + warp) * 2;
    if (ray_base >= num_rays) return;    // warp-uniform
    const int ray   = ray_base + half;
    const int ray_c = min(ray, num_rays - 1);   // clamped for loads

    const float4 wv = reinterpret_cast<const float4*>(weights   + (size_t)ray_c * ND)[hl];
    const float4 ov = reinterpret_cast<const float4*>(s_offsets + (size_t)ray_c * ND)[hl];

    // ---- in-lane partials + segmented inclusive scan (width 16) ----
    const float p1 = wv.x;
    const float p2 = p1 + wv.y;
    const float p3 = p2 + wv.z;
    const float p4 = p3 + wv.w;
    float scan = p4;
    #pragma unroll
    for (int d = 1; d < 16; d <<= 1) {
        float v = __shfl_up_sync(FULL, scan, d, 16);
        if (hl >= d) scan += v;
    }
    const float e0    = scan - p4;                      // exclusive prefix
    const float total = __shfl_sync(FULL, scan, 15, 16);
    const float pad   = fmaxf(EPS - total, 0.0f);
    const float inv   = __fdividef(1.0f, total + pad);
    const float pad64 = pad * (1.0f / 64.0f);

    const int k0 = 4 * hl;                               // first cdf index this lane owns (+1..+4 computed)
    const float c1 = (e0 + p1 + (float)(k0 + 1) * pad64) * inv;
    const float c2 = (e0 + p2 + (float)(k0 + 2) * pad64) * inv;
    const float c3 = (e0 + p3 + (float)(k0 + 3) * pad64) * inv;
    const float c4 = (scan    + (float)(k0 + 4) * pad64) * inv;

    // fused table s_co[k] = (cdf[k], off[k]), k in [0,64); cdf[4hl] from prev lane
    float c4p = __shfl_up_sync(FULL, c4, 1, 16);
    if (hl == 0) c4p = 0.0f;
    float2* co = s_co[warp][half];
    {
        float4* co4 = reinterpret_cast<float4*>(co);
        co4[2 * hl]     = make_float4(c4p, ov.x, c1, ov.y);
        co4[2 * hl + 1] = make_float4(c2,  ov.z, c3, ov.w);
    }

    // ---- analytic counts N_k = #{u < cdf[k]} ----
    int n1 = count_u_below(c1);
    int n2 = count_u_below(c2);
    int n3 = count_u_below(c3);
    int n4 = count_u_below(c4);
    n2 = max(n1, n2); n3 = max(n2, n3); n4 = max(n3, n4);   // in-lane monotone
    if (hl == 15) n4 = 32;                                   // cdf[64]=1 exactly

    int ne = __shfl_up_sync(FULL, n4, 1, 16);               // N_{4hl}
    if (hl == 0) ne = 0;

    // cross-lane monotone? (ulp guard; ~never fires)
    if (__ballot_sync(FULL, n1 < ne)) {
        int P = n4;
        #pragma unroll
        for (int d = 1; d < 16; d <<= 1) {
            int v = __shfl_up_sync(FULL, P, d, 16);
            if (hl >= d) P = max(P, v);
        }
        ne = __shfl_up_sync(FULL, P, 1, 16);
        if (hl == 0) ne = 0;
        n1 = max(n1, ne); n2 = max(n2, n1); n3 = max(n3, n2); n4 = P;
    }

    // ---- scatter bin indices: u_i in [N_k, N_{k+1}) -> idx = k+1 ----
    int* sidx = s_idx[warp][half];
    for (int i = ne; i < n1; ++i) sidx[i] = k0 + 1;
    for (int i = n1; i < n2; ++i) sidx[i] = k0 + 2;
    for (int i = n2; i < n3; ++i) sidx[i] = k0 + 3;
    for (int i = n3; i < n4; ++i) sidx[i] = k0 + 4;
    __syncwarp();

    // ---- invert + interpolate two u's per lane: j0=2hl, j1=2hl+1 ----
    const int2 idx2 = reinterpret_cast<const int2*>(sidx)[hl];
    const int j0 = 2 * hl, j1 = 2 * hl + 1;

    float sn0, sn1;
    int r0, r1;
    {
        const int idx = idx2.x;
        const float u = (float)(2 * j0 + 1) * 0.015625f;
        const float2 L = co[idx - 1];
        const float2 R = co[min(idx, ND - 1)];
        const float num = u - L.x, den = R.x - L.x;
        float t = (den != 0.0f) ? __fdividef(num, den) : ((num > 0.0f) ? 1.0f : 0.0f);
        t = fminf(fmaxf(t, 0.0f), 1.0f);
        sn0 = fmaf(t, R.y - L.y, L.y);
        r0 = idx;
        while (r0 < ND && co[r0].y <= sn0) ++r0;
    }
    {
        const int idx = idx2.y;
        const float u = (float)(2 * j1 + 1) * 0.015625f;
        const float2 L = co[idx - 1];
        const float2 R = co[min(idx, ND - 1)];
        const float num = u - L.x, den = R.x - L.x;
        float t = (den != 0.0f) ? __fdividef(num, den) : ((num > 0.0f) ? 1.0f : 0.0f);
        t = fminf(fmaxf(t, 0.0f), 1.0f);
        sn1 = fmaf(t, R.y - L.y, L.y);
        r1 = idx;
        while (r1 < ND && co[r1].y <= sn1) ++r1;
    }

    // analytic b-ranks valid unless any sn hit an offset exactly (rare)
    int rb0 = ne, rb1 = n1, rb2 = n2, rb3 = n3;
    if (__ballot_sync(FULL, (r0 != idx2.x) || (r1 != idx2.y))) {
        reinterpret_cast<float2*>(s_new[warp][half])[hl] = make_float2(sn0, sn1);
        __syncwarp();
        const float* a = s_new[warp][half];
        const float bv[4] = {ov.x, ov.y, ov.z, ov.w};
        int rb[4];
        #pragma unroll
        for (int m = 0; m < 4; ++m) {
            int l = 0, h = NS;
            #pragma unroll
            for (int it = 0; it < 6; ++it) {
                if (l < h) { int mid = (l + h) >> 1; if (a[mid] < bv[m]) l = mid + 1; else h = mid; }
            }
            rb[m] = l;
        }
        rb0 = rb[0]; rb1 = rb[1]; rb2 = rb[2]; rb3 = rb[3];
    }

    // ---- merge scatter into shared, then dense float4 stores (2 rays) ----
    float* o = s_out[warp] + half * NOUT;
    o[j0 + r0]       = sn0;     // pos_a = i + rank_a
    o[j1 + r1]       = sn1;
    o[k0 + 0 + rb0]  = ov.x;    // pos_b = j + rank_b = j + N_j
    o[k0 + 1 + rb1]  = ov.y;
    o[k0 + 2 + rb2]  = ov.z;
    o[k0 + 3 + rb3]  = ov.w;
    __syncwarp();

    const int valid4 = min(48, (num_rays - ray_base) * (NOUT / 4));
    const float4* so = reinterpret_cast<const float4*>(s_out[warp]);
    float4* og = reinterpret_cast<float4*>(out + (size_t)ray_base * NOUT);
    if (lane < valid4)      og[lane]      = so[lane];
    if (lane + 32 < valid4) og[lane + 32] = so[lane + 32];
}

extern "C" void kernel_launch(void* const* d_in, const int* in_sizes, int n_in,
                              void* d_out, int out_size) {
    const float* weights   = (const float*)d_in[0];
    const float* s_offsets = (const float*)d_in[1];
    float* out = (float*)d_out;

    const int num_rays = in_sizes[0] / ND;
    const int rays_per_block = WPB * 2;
    const int blocks = (num_rays + rays_per_block - 1) / rays_per_block;
    pdf_sampler_kernel<<<blocks, WPB * 32>>>(weights, s_offsets, out, num_rays);
}

// round 8
// speedup vs baseline: 1.7482x; 1.0597x over previous
#include <cuda_runtime.h>
#include <cuda_bf16.h>
#include <cstdint>

// PDF sampler: 2 rays/warp (16 lanes/ray, 4 elems/lane), owner-computes model.
// The lane owning cdf bins k0+1..k0+4 interpolates every u falling in its bins
// entirely from registers and scatters results to their FINAL merged positions.
// No cdf table, no idx round-trip, no shared gathers.

#define ND 64
#define NS 32
#define NOUT 96
#define EPS 1e-5f
#define WPB 8
#define FULL 0xffffffffu

static __device__ __forceinline__ int count_u_below(float c) {
    // exact #{ j in [0,32) : (2j+1)/64 < c }
    int n = (int)fmaf(32.0f, c, 0.5f);      // >= truth, <= truth+1
    n = min(max(n, 0), 32);
    if (n > 0 && (float)(2 * n - 1) * 0.015625f >= c) --n;  // exact cmp
    return n;
}

__global__ __launch_bounds__(WPB * 32)
void pdf_sampler_kernel(const float* __restrict__ weights,
                        const float* __restrict__ s_offsets,
                        float* __restrict__ out,
                        int num_rays) {
    __shared__ __align__(16) float s_new[WPB][2][NS];   // fallback only
    __shared__ __align__(16) float s_out[WPB][2 * NOUT];

    const int warp = threadIdx.x >> 5;
    const int lane = threadIdx.x & 31;
    const int half = lane >> 4;          // ray within warp
    const int hl   = lane & 15;          // lane within 16-lane segment
    const int k0   = 4 * hl;

    const int ray_base = (blockIdx.x * WPB + warp) * 2;
    if (ray_base >= num_rays) return;    // warp-uniform
    const int ray   = ray_base + half;
    const int ray_c = min(ray, num_rays - 1);

    const float4 wv = reinterpret_cast<const float4*>(weights   + (size_t)ray_c * ND)[hl];
    const float4 ov = reinterpret_cast<const float4*>(s_offsets + (size_t)ray_c * ND)[hl];

    // ---- in-lane partials + segmented inclusive scan (width 16) ----
    const float p1 = wv.x;
    const float p2 = p1 + wv.y;
    const float p3 = p2 + wv.z;
    const float p4 = p3 + wv.w;
    float scan = p4;
    #pragma unroll
    for (int d = 1; d < 16; d <<= 1) {
        float v = __shfl_up_sync(FULL, scan, d, 16);
        if (hl >= d) scan += v;
    }
    const float e0    = scan - p4;                      // exclusive prefix
    const float total = __shfl_sync(FULL, scan, 15, 16);
    const float pad   = fmaxf(EPS - total, 0.0f);
    const float inv   = __fdividef(1.0f, total + pad);
    const float pad64 = pad * (1.0f / 64.0f);

    const float c1 = (e0 + p1 + (float)(k0 + 1) * pad64) * inv;  // cdf[k0+1]
    const float c2 = (e0 + p2 + (float)(k0 + 2) * pad64) * inv;
    const float c3 = (e0 + p3 + (float)(k0 + 3) * pad64) * inv;
    const float c4 = (scan    + (float)(k0 + 4) * pad64) * inv;

    float c0 = __shfl_up_sync(FULL, c4, 1, 16);                  // cdf[k0]
    if (hl == 0) c0 = 0.0f;

    // ---- analytic counts N_k = #{u < cdf[k]} ----
    int n1 = count_u_below(c1);
    int n2 = count_u_below(c2);
    int n3 = count_u_below(c3);
    int n4 = count_u_below(c4);
    n2 = max(n1, n2); n3 = max(n2, n3); n4 = max(n3, n4);        // in-lane monotone
    if (hl == 15) n4 = 32;                                        // cdf[64]=1 exactly

    int ne = __shfl_up_sync(FULL, n4, 1, 16);                    // N_{k0}
    if (hl == 0) ne = 0;

    // cross-lane monotone? (ulp guard; ~never fires)
    if (__ballot_sync(FULL, n1 < ne)) {
        int P = n4;
        #pragma unroll
        for (int d = 1; d < 16; d <<= 1) {
            int v = __shfl_up_sync(FULL, P, d, 16);
            if (hl >= d) P = max(P, v);
        }
        ne = __shfl_up_sync(FULL, P, 1, 16);
        if (hl == 0) ne = 0;
        n1 = max(n1, ne); n2 = max(n2, n1); n3 = max(n3, n2); n4 = P;
    }

    // m=4 right-side values (next lane's ov.x / own c4); hl==15: ir clamps to 63
    float c4x = c4;
    float o4x = __shfl_down_sync(FULL, ov.x, 1, 16);
    if (hl == 15) { c4x = c3; o4x = ov.w; }

    float* o = s_out[warp] + half * NOUT;
    const float* goff = s_offsets + (size_t)ray_c * ND;          // rare deep-probe only

    // ---- owner loop: interpolate every u in this lane's bins, scatter to
    //      FINAL merged position j + rank_a ----
    bool anytie = false;
    for (int j = ne; j < n4; ++j) {
        float cl, cr, ol, orr; int idx;
        if (j < n1)      { cl = c0; cr = c1;  ol = ov.x; orr = ov.y; idx = k0 + 1; }
        else if (j < n2) { cl = c1; cr = c2;  ol = ov.y; orr = ov.z; idx = k0 + 2; }
        else if (j < n3) { cl = c2; cr = c3;  ol = ov.z; orr = ov.w; idx = k0 + 3; }
        else             { cl = c3; cr = c4x; ol = ov.w; orr = o4x; idx = k0 + 4; }
        const float u   = fmaf((float)j, 0.03125f, 0.015625f);  // (2j+1)/64 exact
        const float num = u - cl, den = cr - cl;
        float t = (den != 0.0f) ? __fdividef(num, den) : ((num > 0.0f) ? 1.0f : 0.0f);
        t = fminf(fmaxf(t, 0.0f), 1.0f);
        const float sn = fmaf(t, orr - ol, ol);          // ol <= sn <= orr (monotone rounding)
        int r = idx;                                     // rank_a = idx unless sn == off[idx]
        if (idx < ND && sn >= orr) {                     // equality only (sn<=orr proven)
            ++r;
            while (r < ND && goff[r] <= sn) ++r;         // duplicate offsets (rare)
            anytie = true;
        }
        o[j + r] = sn;
    }

    // ---- b-ranks: analytic unless any tie broke strictness (rare) ----
    int rb0 = ne, rb1 = n1, rb2 = n2, rb3 = n3;
    if (__ballot_sync(FULL, anytie)) {                   // warp-uniform branch
        float* sN = s_new[warp][half];
        for (int j = ne; j < n4; ++j) {                  // recompute sn into s_new
            float cl, cr, ol, orr;
            if (j < n1)      { cl = c0; cr = c1;  ol = ov.x; orr = ov.y; }
            else if (j < n2) { cl = c1; cr = c2;  ol = ov.y; orr = ov.z; }
            else if (j < n3) { cl = c2; cr = c3;  ol = ov.z; orr = ov.w; }
            else             { cl = c3; cr = c4x; ol = ov.w; orr = o4x; }
            const float u   = fmaf((float)j, 0.03125f, 0.015625f);
            const float num = u - cl, den = cr - cl;
            float t = (den != 0.0f) ? __fdividef(num, den) : ((num > 0.0f) ? 1.0f : 0.0f);
            t = fminf(fmaxf(t, 0.0f), 1.0f);
            sN[j] = fmaf(t, orr - ol, ol);
        }
        __syncwarp();
        const float bv[4] = {ov.x, ov.y, ov.z, ov.w};
        int rb[4];
        #pragma unroll
        for (int m = 0; m < 4; ++m) {
            int l = 0, h = NS;
            #pragma unroll
            for (int it = 0; it < 6; ++it) {
                if (l < h) { int mid = (l + h) >> 1; if (sN[mid] < bv[m]) l = mid + 1; else h = mid; }
            }
            rb[m] = l;
        }
        rb0 = rb[0]; rb1 = rb[1]; rb2 = rb[2]; rb3 = rb[3];
    }

    o[k0 + 0 + rb0] = ov.x;     // pos_b = k + rank_b = k + N_k
    o[k0 + 1 + rb1] = ov.y;
    o[k0 + 2 + rb2] = ov.z;
    o[k0 + 3 + rb3] = ov.w;
    __syncwarp();

    // ---- dense float4 output (2 rays = 192 contiguous floats) ----
    const int valid4 = min(48, (num_rays - ray_base) * (NOUT / 4));
    const float4* so = reinterpret_cast<const float4*>(s_out[warp]);
    float4* og = reinterpret_cast<float4*>(out + (size_t)ray_base * NOUT);
    if (lane < valid4)      og[lane]      = so[lane];
    if (lane + 32 < valid4) og[lane + 32] = so[lane + 32];
}

extern "C" void kernel_launch(void* const* d_in, const int* in_sizes, int n_in,
                              void* d_out, int out_size) {
    const float* weights   = (const float*)d_in[0];
    const float* s_offsets = (const float*)d_in[1];
    float* out = (float*)d_out;

    const int num_rays = in_sizes[0] / ND;
    const int rays_per_block = WPB * 2;
    const int blocks = (num_rays + rays_per_block - 1) / rays_per_block;
    pdf_sampler_kernel<<<blocks, WPB * 32>>>(weights, s_offsets, out, num_rays);
}

// round 9
// speedup vs baseline: 1.7893x; 1.0235x over previous
#include <cuda_runtime.h>
#include <cuda_bf16.h>
#include <cstdint>

// PDF sampler: 2 rays/warp (16 lanes/ray, 4 elems/lane), owner-computes model.
// Owner lane interpolates every u in its cdf bins from registers and scatters
// straight to final merged positions. 32-reg build for full occupancy.

#define ND 64
#define NS 32
#define NOUT 96
#define EPS 1e-5f
#define WPB 8
#define FULL 0xffffffffu

static __device__ __forceinline__ int count_u_below(float c) {
    // exact #{ j in [0,32) : (2j+1)/64 < c }
    int n = (int)fmaf(32.0f, c, 0.5f);      // >= truth, <= truth+1
    n = min(max(n, 0), 32);
    if (n > 0 && (float)(2 * n - 1) * 0.015625f >= c) --n;  // exact cmp
    return n;
}

__global__ __launch_bounds__(WPB * 32, 8)
void pdf_sampler_kernel(const float* __restrict__ weights,
                        const float* __restrict__ s_offsets,
                        float* __restrict__ out,
                        int num_rays) {
    __shared__ __align__(16) float s_new[WPB][2][NS];   // sorted new samples
    __shared__ __align__(16) float s_out[WPB][2 * NOUT];

    const int warp = threadIdx.x >> 5;
    const int lane = threadIdx.x & 31;
    const int half = lane >> 4;          // ray within warp
    const int hl   = lane & 15;          // lane within 16-lane segment
    const int k0   = 4 * hl;

    const int ray_base = (blockIdx.x * WPB + warp) * 2;
    if (ray_base >= num_rays) return;    // warp-uniform
    const int ray   = ray_base + half;
    const int ray_c = min(ray, num_rays - 1);

    const float4 wv = reinterpret_cast<const float4*>(weights   + (size_t)ray_c * ND)[hl];
    const float4 ov = reinterpret_cast<const float4*>(s_offsets + (size_t)ray_c * ND)[hl];

    // ---- in-lane partials + segmented inclusive scan (width 16) ----
    const float p1 = wv.x;
    const float p2 = p1 + wv.y;
    const float p3 = p2 + wv.z;
    const float p4 = p3 + wv.w;
    float scan = p4;
    #pragma unroll
    for (int d = 1; d < 16; d <<= 1) {
        float v = __shfl_up_sync(FULL, scan, d, 16);
        if (hl >= d) scan += v;
    }
    const float e0    = scan - p4;                      // exclusive prefix
    const float total = __shfl_sync(FULL, scan, 15, 16);
    const float pad   = fmaxf(EPS - total, 0.0f);
    const float inv   = __fdividef(1.0f, total + pad);
    const float pad64 = pad * (1.0f / 64.0f);

    const float c1 = (e0 + p1 + (float)(k0 + 1) * pad64) * inv;  // cdf[k0+1]
    const float c2 = (e0 + p2 + (float)(k0 + 2) * pad64) * inv;
    const float c3 = (e0 + p3 + (float)(k0 + 3) * pad64) * inv;
    const float c4 = (scan    + (float)(k0 + 4) * pad64) * inv;

    float c0 = __shfl_up_sync(FULL, c4, 1, 16);                  // cdf[k0]
    if (hl == 0) c0 = 0.0f;

    // ---- analytic counts N_k = #{u < cdf[k]} ----
    int n1 = count_u_below(c1);
    int n2 = count_u_below(c2);
    int n3 = count_u_below(c3);
    int n4 = count_u_below(c4);
    n2 = max(n1, n2); n3 = max(n2, n3); n4 = max(n3, n4);        // in-lane monotone
    if (hl == 15) n4 = 32;                                        // cdf[64]=1 exactly

    int ne = __shfl_up_sync(FULL, n4, 1, 16);                    // N_{k0}
    if (hl == 0) ne = 0;

    // cross-lane monotone? (ulp guard; ~never fires)
    if (__ballot_sync(FULL, n1 < ne)) {
        int P = n4;
        #pragma unroll
        for (int d = 1; d < 16; d <<= 1) {
            int v = __shfl_up_sync(FULL, P, d, 16);
            if (hl >= d) P = max(P, v);
        }
        ne = __shfl_up_sync(FULL, P, 1, 16);
        if (hl == 0) ne = 0;
        n1 = max(n1, ne); n2 = max(n2, n1); n3 = max(n3, n2); n4 = P;
    }

    // m=4 right-side values (next lane's ov.x / own c4); hl==15: ir clamps to 63
    float c4x = c4;
    float o4x = __shfl_down_sync(FULL, ov.x, 1, 16);
    if (hl == 15) { c4x = c3; o4x = ov.w; }

    float* o  = s_out[warp] + half * NOUT;
    float* sN = s_new[warp][half];
    const float* goff = s_offsets + (size_t)ray_c * ND;          // rare deep-probe only

    // ---- owner loop: interpolate every u in this lane's bins, scatter to
    //      FINAL merged position j + rank_a; also record sorted sn ----
    bool anytie = false;
    for (int j = ne; j < n4; ++j) {
        float cl, cr, ol, orr; int idx;
        if (j < n1)      { cl = c0; cr = c1;  ol = ov.x; orr = ov.y; idx = k0 + 1; }
        else if (j < n2) { cl = c1; cr = c2;  ol = ov.y; orr = ov.z; idx = k0 + 2; }
        else if (j < n3) { cl = c2; cr = c3;  ol = ov.z; orr = ov.w; idx = k0 + 3; }
        else             { cl = c3; cr = c4x; ol = ov.w; orr = o4x; idx = k0 + 4; }
        const float u   = fmaf((float)j, 0.03125f, 0.015625f);  // (2j+1)/64 exact
        const float num = u - cl, den = cr - cl;
        float t = (den != 0.0f) ? __fdividef(num, den) : ((num > 0.0f) ? 1.0f : 0.0f);
        t = fminf(fmaxf(t, 0.0f), 1.0f);
        const float sn = fmaf(t, orr - ol, ol);          // ol <= sn <= orr (monotone rounding)
        sN[j] = sn;
        int r = idx;                                     // rank_a = idx unless sn == off[idx]
        if (idx < ND && sn >= orr) {                     // equality only (sn<=orr proven)
            ++r;
            while (r < ND && goff[r] <= sn) ++r;         // duplicate offsets (rare)
            anytie = true;
        }
        o[j + r] = sn;
    }

    // ---- b-ranks: analytic unless any tie broke strictness (rare) ----
    int rb0 = ne, rb1 = n1, rb2 = n2, rb3 = n3;
    if (__ballot_sync(FULL, anytie)) {                   // warp-uniform branch
        __syncwarp();
        const float bv[4] = {ov.x, ov.y, ov.z, ov.w};
        int rb[4];
        #pragma unroll
        for (int m = 0; m < 4; ++m) {
            int l = 0, h = NS;
            #pragma unroll
            for (int it = 0; it < 6; ++it) {
                if (l < h) { int mid = (l + h) >> 1; if (sN[mid] < bv[m]) l = mid + 1; else h = mid; }
            }
            rb[m] = l;
        }
        rb0 = rb[0]; rb1 = rb[1]; rb2 = rb[2]; rb3 = rb[3];
    }

    o[k0 + 0 + rb0] = ov.x;     // pos_b = k + rank_b = k + N_k
    o[k0 + 1 + rb1] = ov.y;
    o[k0 + 2 + rb2] = ov.z;
    o[k0 + 3 + rb3] = ov.w;
    __syncwarp();

    // ---- dense float4 output (2 rays = 192 contiguous floats) ----
    const int valid4 = min(48, (num_rays - ray_base) * (NOUT / 4));
    const float4* so = reinterpret_cast<const float4*>(s_out[warp]);
    float4* og = reinterpret_cast<float4*>(out + (size_t)ray_base * NOUT);
    if (lane < valid4)      og[lane]      = so[lane];
    if (lane + 32 < valid4) og[lane + 32] = so[lane + 32];
}

extern "C" void kernel_launch(void* const* d_in, const int* in_sizes, int n_in,
                              void* d_out, int out_size) {
    const float* weights   = (const float*)d_in[0];
    const float* s_offsets = (const float*)d_in[1];
    float* out = (float*)d_out;

    const int num_rays = in_sizes[0] / ND;
    const int rays_per_block = WPB * 2;
    const int blocks = (num_rays + rays_per_block - 1) / rays_per_block;
    pdf_sampler_kernel<<<blocks, WPB * 32>>>(weights, s_offsets, out, num_rays);
}

// round 10
// speedup vs baseline: 2.0092x; 1.1228x over previous
#include <cuda_runtime.h>
#include <cuda_bf16.h>
#include <cstdint>

// PDF sampler: 2 rays/warp (16 lanes/ray, 4 elems/lane), owner-computes,
// bin-major owner loops with hoisted reciprocal. 32-reg full-occupancy build.

#define ND 64
#define NS 32
#define NOUT 96
#define EPS 1e-5f
#define WPB 8
#define FULL 0xffffffffu

static __device__ __forceinline__ int count_u_below(float c) {
    // exact #{ j in [0,32) : (2j+1)/64 < c }
    int n = (int)fmaf(32.0f, c, 0.5f);      // >= truth, <= truth+1
    n = min(max(n, 0), 32);
    if (n > 0 && (float)(2 * n - 1) * 0.015625f >= c) --n;  // exact cmp
    return n;
}

__global__ __launch_bounds__(WPB * 32, 8)
void pdf_sampler_kernel(const float* __restrict__ weights,
                        const float* __restrict__ s_offsets,
                        float* __restrict__ out,
                        int num_rays) {
    __shared__ __align__(16) float s_new[WPB][2][NS];   // sorted new samples
    __shared__ __align__(16) float s_out[WPB][2 * NOUT];

    const int warp = threadIdx.x >> 5;
    const int lane = threadIdx.x & 31;
    const int half = lane >> 4;          // ray within warp
    const int hl   = lane & 15;          // lane within 16-lane segment
    const int k0   = 4 * hl;

    const int ray_base = (blockIdx.x * WPB + warp) * 2;
    if (ray_base >= num_rays) return;    // warp-uniform
    const int ray   = ray_base + half;
    const int ray_c = min(ray, num_rays - 1);

    const float4 wv = reinterpret_cast<const float4*>(weights   + (size_t)ray_c * ND)[hl];
    const float4 ov = reinterpret_cast<const float4*>(s_offsets + (size_t)ray_c * ND)[hl];

    // ---- in-lane partials + segmented inclusive scan (width 16) ----
    const float p1 = wv.x;
    const float p2 = p1 + wv.y;
    const float p3 = p2 + wv.z;
    const float p4 = p3 + wv.w;
    float scan = p4;
    #pragma unroll
    for (int d = 1; d < 16; d <<= 1) {
        float v = __shfl_up_sync(FULL, scan, d, 16);
        if (hl >= d) scan += v;
    }
    const float e0    = scan - p4;                      // exclusive prefix
    const float total = __shfl_sync(FULL, scan, 15, 16);
    const float pad   = fmaxf(EPS - total, 0.0f);
    const float inv   = __fdividef(1.0f, total + pad);
    const float pad64 = pad * (1.0f / 64.0f);

    const float c1 = (e0 + p1 + (float)(k0 + 1) * pad64) * inv;  // cdf[k0+1]
    const float c2 = (e0 + p2 + (float)(k0 + 2) * pad64) * inv;
    const float c3 = (e0 + p3 + (float)(k0 + 3) * pad64) * inv;
    const float c4 = (scan    + (float)(k0 + 4) * pad64) * inv;

    float c0 = __shfl_up_sync(FULL, c4, 1, 16);                  // cdf[k0]
    if (hl == 0) c0 = 0.0f;

    // ---- analytic counts N_k = #{u < cdf[k]} ----
    int n1 = count_u_below(c1);
    int n2 = count_u_below(c2);
    int n3 = count_u_below(c3);
    int n4 = count_u_below(c4);
    n2 = max(n1, n2); n3 = max(n2, n3); n4 = max(n3, n4);        // in-lane monotone
    if (hl == 15) n4 = 32;                                        // cdf[64]=1 exactly

    int ne = __shfl_up_sync(FULL, n4, 1, 16);                    // N_{k0}
    if (hl == 0) ne = 0;

    // cross-lane monotone? (ulp guard; ~never fires)
    if (__ballot_sync(FULL, n1 < ne)) {
        int P = n4;
        #pragma unroll
        for (int d = 1; d < 16; d <<= 1) {
            int v = __shfl_up_sync(FULL, P, d, 16);
            if (hl >= d) P = max(P, v);
        }
        ne = __shfl_up_sync(FULL, P, 1, 16);
        if (hl == 0) ne = 0;
        n1 = max(n1, ne); n2 = max(n2, n1); n3 = max(n3, n2); n4 = P;
    }

    // m=4 right-side values (next lane's ov.x / own c4); hl==15: ir clamps to 63
    float c4x = c4;
    float o4x = __shfl_down_sync(FULL, ov.x, 1, 16);
    if (hl == 15) { c4x = c3; o4x = ov.w; }

    float* o  = s_out[warp] + half * NOUT;
    float* sN = s_new[warp][half];
    const float* goff = s_offsets + (size_t)ray_c * ND;          // rare deep-probe only

    // ---- bin-major owner loops: per-bin invariants hoisted.
    //      invden = inf when den==0: t = num*inf -> +inf->1 / NaN->0 via clamp,
    //      exactly matching reference nan_to_num + clip (num >= 0 guaranteed). ----
    bool anytie = false;
    #define BIN_LOOP(JLO, JHI, CL, CR, OL, ORR, IDX)                          \
    {                                                                         \
        const float invden = __fdividef(1.0f, (CR) - (CL));                   \
        const float dor    = (ORR) - (OL);                                    \
        for (int j = (JLO); j < (JHI); ++j) {                                 \
            const float u  = fmaf((float)j, 0.03125f, 0.015625f);             \
            float t = (u - (CL)) * invden;                                    \
            t = fminf(fmaxf(t, 0.0f), 1.0f);                                  \
            const float sn = fmaf(t, dor, (OL));                              \
            sN[j] = sn;                                                       \
            int r = (IDX);                                                    \
            if ((IDX) < ND && sn >= (ORR)) {                                  \
                ++r;                                                          \
                while (r < ND && goff[r] <= sn) ++r;                          \
                anytie = true;                                                \
            }                                                                 \
            o[j + r] = sn;                                                    \
        }                                                                     \
    }
    BIN_LOOP(ne, n1, c0, c1,  ov.x, ov.y, k0 + 1)
    BIN_LOOP(n1, n2, c1, c2,  ov.y, ov.z, k0 + 2)
    BIN_LOOP(n2, n3, c2, c3,  ov.z, ov.w, k0 + 3)
    BIN_LOOP(n3, n4, c3, c4x, ov.w, o4x,  k0 + 4)
    #undef BIN_LOOP

    // ---- b-ranks: analytic unless any tie broke strictness (rare) ----
    int rb0 = ne, rb1 = n1, rb2 = n2, rb3 = n3;
    if (__ballot_sync(FULL, anytie)) {                   // warp-uniform branch
        __syncwarp();
        const float bv[4] = {ov.x, ov.y, ov.z, ov.w};
        int rb[4];
        #pragma unroll
        for (int m = 0; m < 4; ++m) {
            int l = 0, h = NS;
            #pragma unroll
            for (int it = 0; it < 6; ++it) {
                if (l < h) { int mid = (l + h) >> 1; if (sN[mid] < bv[m]) l = mid + 1; else h = mid; }
            }
            rb[m] = l;
        }
        rb0 = rb[0]; rb1 = rb[1]; rb2 = rb[2]; rb3 = rb[3];
    }

    o[k0 + 0 + rb0] = ov.x;     // pos_b = k + rank_b = k + N_k
    o[k0 + 1 + rb1] = ov.y;
    o[k0 + 2 + rb2] = ov.z;
    o[k0 + 3 + rb3] = ov.w;
    __syncwarp();

    // ---- dense float4 output (2 rays = 192 contiguous floats) ----
    const int valid4 = min(48, (num_rays - ray_base) * (NOUT / 4));
    const float4* so = reinterpret_cast<const float4*>(s_out[warp]);
    float4* og = reinterpret_cast<float4*>(out + (size_t)ray_base * NOUT);
    if (lane < valid4)      og[lane]      = so[lane];
    if (lane + 32 < valid4) og[lane + 32] = so[lane + 32];
}

extern "C" void kernel_launch(void* const* d_in, const int* in_sizes, int n_in,
                              void* d_out, int out_size) {
    const float* weights   = (const float*)d_in[0];
    const float* s_offsets = (const float*)d_in[1];
    float* out = (float*)d_out;

    const int num_rays = in_sizes[0] / ND;
    const int rays_per_block = WPB * 2;
    const int blocks = (num_rays + rays_per_block - 1) / rays_per_block;
    pdf_sampler_kernel<<<blocks, WPB * 32>>>(weights, s_offsets, out, num_rays);
}

// round 11
// speedup vs baseline: 2.1001x; 1.0453x over previous
#include <cuda_runtime.h>
#include <cuda_bf16.h>
#include <cstdint>

// PDF sampler: 2 rays/warp (16 lanes/ray, 4 elems/lane), owner-computes,
// bin-major owner loops, cheap ceil-based counts, pad==0 fast path,
// saturate-fused clamp. 32-reg full-occupancy build.

#define ND 64
#define NS 32
#define NOUT 96
#define EPS 1e-5f
#define WPB 8
#define FULL 0xffffffffu

static __device__ __forceinline__ int count_u_below(float c) {
    // ~#{ j in [0,32) : (2j+1)/64 < c } = clamp(ceil(32c - 0.5), 0, 32).
    // May be off by 1 only when 32c-0.5 rounds across an integer (u_j == c
    // at ulp level) -- value-continuous boundary; merge stays correct via
    // the probe/anytie machinery and monotone enforcement below.
    return min(max(__float2int_ru(fmaf(32.0f, c, -0.5f)), 0), 32);
}

__global__ __launch_bounds__(WPB * 32, 8)
void pdf_sampler_kernel(const float* __restrict__ weights,
                        const float* __restrict__ s_offsets,
                        float* __restrict__ out,
                        int num_rays) {
    __shared__ __align__(16) float s_new[WPB][2][NS];   // sorted new samples
    __shared__ __align__(16) float s_out[WPB][2 * NOUT];

    const int warp = threadIdx.x >> 5;
    const int lane = threadIdx.x & 31;
    const int half = lane >> 4;          // ray within warp
    const int hl   = lane & 15;          // lane within 16-lane segment
    const int k0   = 4 * hl;

    const int ray_base = (blockIdx.x * WPB + warp) * 2;
    if (ray_base >= num_rays) return;    // warp-uniform
    const int ray   = ray_base + half;
    const int ray_c = min(ray, num_rays - 1);

    const float4 wv = reinterpret_cast<const float4*>(weights   + (size_t)ray_c * ND)[hl];
    const float4 ov = reinterpret_cast<const float4*>(s_offsets + (size_t)ray_c * ND)[hl];

    // ---- in-lane partials + segmented inclusive scan (width 16) ----
    const float p1 = wv.x;
    const float p2 = p1 + wv.y;
    const float p3 = p2 + wv.z;
    const float p4 = p3 + wv.w;
    float scan = p4;
    #pragma unroll
    for (int d = 1; d < 16; d <<= 1) {
        float v = __shfl_up_sync(FULL, scan, d, 16);
        if (hl >= d) scan += v;
    }
    const float e0    = scan - p4;                      // exclusive prefix
    const float total = __shfl_sync(FULL, scan, 15, 16);
    const float pad   = fmaxf(EPS - total, 0.0f);
    const float inv   = __fdividef(1.0f, total + pad);

    const float cum1 = e0 + p1;
    const float cum2 = e0 + p2;
    const float cum3 = e0 + p3;

    float c1, c2, c3, c4;
    if (__ballot_sync(FULL, pad != 0.0f)) {             // ~never taken
        const float pad64 = pad * (1.0f / 64.0f);
        c1 = (cum1 + (float)(k0 + 1) * pad64) * inv;
        c2 = (cum2 + (float)(k0 + 2) * pad64) * inv;
        c3 = (cum3 + (float)(k0 + 3) * pad64) * inv;
        c4 = (scan + (float)(k0 + 4) * pad64) * inv;
    } else {                                            // pad == 0 fast path
        c1 = cum1 * inv;
        c2 = cum2 * inv;
        c3 = cum3 * inv;
        c4 = scan * inv;
    }

    float c0 = __shfl_up_sync(FULL, c4, 1, 16);         // cdf[k0]
    if (hl == 0) c0 = 0.0f;

    // ---- counts N_k ~ #{u < cdf[k]} ----
    int n1 = count_u_below(c1);
    int n2 = count_u_below(c2);
    int n3 = count_u_below(c3);
    int n4 = count_u_below(c4);
    n2 = max(n1, n2); n3 = max(n2, n3); n4 = max(n3, n4);   // in-lane monotone
    if (hl == 15) n4 = 32;                                   // cdf[64]=1 exactly

    int ne = __shfl_up_sync(FULL, n4, 1, 16);                // N_{k0}
    if (hl == 0) ne = 0;

    // cross-lane monotone? (ulp guard; ~never fires)
    if (__ballot_sync(FULL, n1 < ne)) {
        int P = n4;
        #pragma unroll
        for (int d = 1; d < 16; d <<= 1) {
            int v = __shfl_up_sync(FULL, P, d, 16);
            if (hl >= d) P = max(P, v);
        }
        ne = __shfl_up_sync(FULL, P, 1, 16);
        if (hl == 0) ne = 0;
        n1 = max(n1, ne); n2 = max(n2, n1); n3 = max(n3, n2); n4 = P;
    }

    // bin-4 right-side values (next lane's ov.x / own c4); hl==15: clamp to 63
    float c4x = c4;
    float o4x = __shfl_down_sync(FULL, ov.x, 1, 16);
    if (hl == 15) { c4x = c3; o4x = ov.w; }

    float* o  = s_out[warp] + half * NOUT;
    float* sN = s_new[warp][half];
    const float* goff = s_offsets + (size_t)ray_c * ND;      // rare deep-probe only

    // ---- bin-major owner loops; per-bin invariants hoisted.
    //      invden=inf when den==0: t = num*inf -> +inf->1 / NaN->0 via
    //      __saturatef, matching reference nan_to_num + clip exactly. ----
    bool anytie = false;
    #define BIN_LOOP(JLO, JHI, CL, CR, OL, ORR, IDX, CHK)                     \
    {                                                                         \
        const float invden = __fdividef(1.0f, (CR) - (CL));                   \
        const float dor    = (ORR) - (OL);                                    \
        float u = fmaf((float)(JLO), 0.03125f, 0.015625f);  /* exact */       \
        for (int j = (JLO); j < (JHI); ++j, u += 0.03125f) {                  \
            const float t  = __saturatef((u - (CL)) * invden);                \
            const float sn = fmaf(t, dor, (OL));                              \
            sN[j] = sn;                                                       \
            int r = (IDX);                                                    \
            if ((CHK) && sn >= (ORR)) {                                       \
                ++r;                                                          \
                while (r < ND && goff[r] <= sn) ++r;                          \
                anytie = true;                                                \
            }                                                                 \
            o[j + r] = sn;                                                    \
        }                                                                     \
    }
    BIN_LOOP(ne, n1, c0, c1,  ov.x, ov.y, k0 + 1, true)          // k0+1 <= 61 < ND
    BIN_LOOP(n1, n2, c1, c2,  ov.y, ov.z, k0 + 2, true)
    BIN_LOOP(n2, n3, c2, c3,  ov.z, ov.w, k0 + 3, true)
    BIN_LOOP(n3, n4, c3, c4x, ov.w, o4x,  k0 + 4, (k0 + 4 < ND))
    #undef BIN_LOOP

    // ---- b-ranks: analytic unless a tie broke strictness (rare) ----
    int rb0 = ne, rb1 = n1, rb2 = n2, rb3 = n3;
    if (__ballot_sync(FULL, anytie)) {                   // warp-uniform branch
        __syncwarp();
        const float bv[4] = {ov.x, ov.y, ov.z, ov.w};
        int rb[4];
        #pragma unroll
        for (int m = 0; m < 4; ++m) {
            int l = 0, h = NS;
            #pragma unroll
            for (int it = 0; it < 6; ++it) {
                if (l < h) { int mid = (l + h) >> 1; if (sN[mid] < bv[m]) l = mid + 1; else h = mid; }
            }
            rb[m] = l;
        }
        rb0 = rb[0]; rb1 = rb[1]; rb2 = rb[2]; rb3 = rb[3];
    }

    o[k0 + 0 + rb0] = ov.x;     // pos_b = k + rank_b = k + N_k
    o[k0 + 1 + rb1] = ov.y;
    o[k0 + 2 + rb2] = ov.z;
    o[k0 + 3 + rb3] = ov.w;
    __syncwarp();

    // ---- dense float4 output (2 rays = 192 contiguous floats) ----
    const int valid4 = min(48, (num_rays - ray_base) * (NOUT / 4));
    const float4* so = reinterpret_cast<const float4*>(s_out[warp]);
    float4* og = reinterpret_cast<float4*>(out + (size_t)ray_base * NOUT);
    if (lane < valid4)      og[lane]      = so[lane];
    if (lane + 32 < valid4) og[lane + 32] = so[lane + 32];
}

extern "C" void kernel_launch(void* const* d_in, const int* in_sizes, int n_in,
                              void* d_out, int out_size) {
    const float* weights   = (const float*)d_in[0];
    const float* s_offsets = (const float*)d_in[1];
    float* out = (float*)d_out;

    const int num_rays = in_sizes[0] / ND;
    const int rays_per_block = WPB * 2;
    const int blocks = (num_rays + rays_per_block - 1) / rays_per_block;
    pdf_sampler_kernel<<<blocks, WPB * 32>>>(weights, s_offsets, out, num_rays);
}